// round 4
// baseline (speedup 1.0000x reference)
#include <cuda_runtime.h>

// SSIM loss, single fused kernel, f32x2-packed separable blur.
// pred/target: (16,3,512,512) f32. Output: scalar f32 = 1 - mean(ssim_map).

#define RAD 5
#define TX 32
#define TY 32
#define PH 42               // TY + 2*RAD
#define PW 42               // TX + 2*RAD
#define HB_PITCH 34         // float2 pitch for hb12/hb34 (272B ≡ 16 mod 128)
#define HB5_PITCH 36        // float pitch for hb5 (144B ≡ 16 mod 128)
#define IMG 512
#define NIMG 48
#define TILES 256           // 16 x 16 tiles per image
#define NBLK (TILES * NIMG) // 12288
#define SSIM_C1 1.0e-4f
#define SSIM_C2 9.0e-4f

__device__ float g_bsum[NBLK];
__device__ int g_cnt;       // zero-init; last block resets each run

union F2U { float2 f; unsigned long long u; };

__device__ __forceinline__ unsigned long long pack2(float x, float y) {
    unsigned long long r;
    asm("mov.b64 %0, {%1, %2};" : "=l"(r) : "f"(x), "f"(y));
    return r;
}
__device__ __forceinline__ unsigned long long fma2(unsigned long long a,
                                                   unsigned long long b,
                                                   unsigned long long c) {
    unsigned long long d;
    asm("fma.rn.f32x2 %0, %1, %2, %3;" : "=l"(d) : "l"(a), "l"(b), "l"(c));
    return d;
}
__device__ __forceinline__ unsigned long long mul2(unsigned long long a,
                                                   unsigned long long b) {
    unsigned long long d;
    asm("mul.rn.f32x2 %0, %1, %2;" : "=l"(d) : "l"(a), "l"(b));
    return d;
}

__global__ __launch_bounds__(256)
void ssim_fused(const float* __restrict__ pred,
                const float* __restrict__ target,
                float* __restrict__ out)
{
    __shared__ float2 spt[PH][PW];          // (p,t) interleaved
    __shared__ float2 hb12[PH][HB_PITCH];   // (h(p), h(t))
    __shared__ float2 hb34[PH][HB_PITCH];   // (h(p^2), h(t^2))
    __shared__ float  hb5[PH][HB5_PITCH];   // h(p*t)
    __shared__ float  wsum[8];
    __shared__ double dsum[8];
    __shared__ int    s_last;

    // Normalized 1-D Gaussian, sigma=1.5, size 11.
    const float GWs[11] = {
        0.00102838f, 0.00759876f, 0.03600077f, 0.10936069f, 0.21300553f,
        0.26601173f,
        0.21300553f, 0.10936069f, 0.03600077f, 0.00759876f, 0.00102838f
    };
    unsigned long long GWp[11];
    #pragma unroll
    for (int k = 0; k < 11; k++) GWp[k] = pack2(GWs[k], GWs[k]);
    const unsigned long long NEG1 = pack2(-1.0f, -1.0f);

    const int tid  = threadIdx.x;
    const int lane = tid & 31;
    const int wrp  = tid >> 5;

    const int tile_x = blockIdx.x & 15;
    const int tile_y = blockIdx.x >> 4;
    const int bid    = blockIdx.y * TILES + blockIdx.x;
    const float* pb = pred   + (size_t)blockIdx.y * IMG * IMG;
    const float* tb = target + (size_t)blockIdx.y * IMG * IMG;
    const int x0 = tile_x * TX - RAD;
    const int y0 = tile_y * TY - RAD;

    // ---- Phase 1: load 42x42 halo, interleave (p,t) ---------------------
    #pragma unroll 1
    for (int r = wrp; r < PH; r += 8) {
        const int gy = y0 + r;
        const bool rok = ((unsigned)gy < (unsigned)IMG);
        const float* prow = pb + gy * IMG;
        const float* trow = tb + gy * IMG;
        {
            const int gx = x0 + lane;
            const bool ok = rok && ((unsigned)gx < (unsigned)IMG);
            spt[r][lane] = make_float2(ok ? __ldg(prow + gx) : 0.f,
                                       ok ? __ldg(trow + gx) : 0.f);
        }
        if (lane < PW - 32) {
            const int gx = x0 + lane + 32;
            const bool ok = rok && ((unsigned)gx < (unsigned)IMG);
            spt[r][lane + 32] = make_float2(ok ? __ldg(prow + gx) : 0.f,
                                            ok ? __ldg(trow + gx) : 0.f);
        }
    }
    __syncthreads();

    // ---- Phase 2: horizontal blur. Warp w owns output cols 4w..4w+3; ----
    // rows come from lane (r = lane, then 32+lane). No div/mod anywhere.
    {
        const int cx = wrp * 4;
        #pragma unroll
        for (int step = 0; step < 2; step++) {
            const int r = lane + 32 * step;
            if (step == 0 || r < PH) {
                float4 raw[7];
                const float4* rp = reinterpret_cast<const float4*>(&spt[r][cx]);
                #pragma unroll
                for (int q = 0; q < 7; q++) raw[q] = rp[q];

                F2U acc12[4], acc34[4];
                float acc5[4];
                #pragma unroll
                for (int j = 0; j < 4; j++) {
                    acc12[j].f = make_float2(0.f, 0.f);
                    acc34[j].f = make_float2(0.f, 0.f);
                    acc5[j] = 0.f;
                }

                #pragma unroll
                for (int k = 0; k < 14; k++) {
                    F2U e;
                    e.f.x = (k & 1) ? raw[k >> 1].z : raw[k >> 1].x;
                    e.f.y = (k & 1) ? raw[k >> 1].w : raw[k >> 1].y;
                    F2U sq; sq.u = mul2(e.u, e.u);
                    const float x = e.f.x * e.f.y;
                    #pragma unroll
                    for (int j = 0; j < 4; j++) {
                        const int w = k - j;
                        if (w >= 0 && w < 11) {
                            acc12[j].u = fma2(GWp[w], e.u,  acc12[j].u);
                            acc34[j].u = fma2(GWp[w], sq.u, acc34[j].u);
                            acc5[j]    = fmaf(GWs[w], x, acc5[j]);
                        }
                    }
                }

                *reinterpret_cast<float4*>(&hb12[r][cx]) =
                    make_float4(acc12[0].f.x, acc12[0].f.y, acc12[1].f.x, acc12[1].f.y);
                *reinterpret_cast<float4*>(&hb12[r][cx + 2]) =
                    make_float4(acc12[2].f.x, acc12[2].f.y, acc12[3].f.x, acc12[3].f.y);
                *reinterpret_cast<float4*>(&hb34[r][cx]) =
                    make_float4(acc34[0].f.x, acc34[0].f.y, acc34[1].f.x, acc34[1].f.y);
                *reinterpret_cast<float4*>(&hb34[r][cx + 2]) =
                    make_float4(acc34[2].f.x, acc34[2].f.y, acc34[3].f.x, acc34[3].f.y);
                *reinterpret_cast<float4*>(&hb5[r][cx]) =
                    make_float4(acc5[0], acc5[1], acc5[2], acc5[3]);
            }
        }
    }
    __syncthreads();

    // ---- Phase 3: vertical blur, ALL 8 warps, 4 rows/thread + SSIM ------
    float ssum;
    {
        const int c  = lane;
        const int yb = wrp * 4;

        F2U a12[4], a34[4];
        float a5[4];
        #pragma unroll
        for (int j = 0; j < 4; j++) {
            a12[j].f = make_float2(0.f, 0.f);
            a34[j].f = make_float2(0.f, 0.f);
            a5[j] = 0.f;
        }

        #pragma unroll
        for (int k = 0; k < 14; k++) {
            F2U h12; h12.f = hb12[yb + k][c];
            F2U h34; h34.f = hb34[yb + k][c];
            const float h5 = hb5[yb + k][c];
            #pragma unroll
            for (int j = 0; j < 4; j++) {
                const int w = k - j;
                if (w >= 0 && w < 11) {
                    a12[j].u = fma2(GWp[w], h12.u, a12[j].u);
                    a34[j].u = fma2(GWp[w], h34.u, a34[j].u);
                    a5[j]    = fmaf(GWs[w], h5, a5[j]);
                }
            }
        }

        float num[4], den[4];
        #pragma unroll
        for (int j = 0; j < 4; j++) {
            F2U musq; musq.u = mul2(a12[j].u, a12[j].u);        // (mu1^2, mu2^2)
            F2U sig;  sig.u  = fma2(NEG1, musq.u, a34[j].u);    // (sig1^2, sig2^2)
            const float mu12 = a12[j].f.x * a12[j].f.y;
            const float s12v = a5[j] - mu12;
            num[j] = fmaf(2.f, mu12, SSIM_C1) * fmaf(2.f, s12v, SSIM_C2);
            den[j] = (musq.f.x + musq.f.y + SSIM_C1) * (sig.f.x + sig.f.y + SSIM_C2);
        }

        // One division per 4 pixels (den >= ~9e-8; 4-way product stays normal).
        const float n01 = fmaf(num[0], den[1], num[1] * den[0]);
        const float d01 = den[0] * den[1];
        const float n23 = fmaf(num[2], den[3], num[3] * den[2]);
        const float d23 = den[2] * den[3];
        const float nall = fmaf(n01, d23, n23 * d01);
        const float dall = d01 * d23;
        ssum = __fdividef(nall, dall);
    }

    #pragma unroll
    for (int o = 16; o > 0; o >>= 1)
        ssum += __shfl_xor_sync(0xffffffffu, ssum, o);
    if (lane == 0) wsum[wrp] = ssum;
    __syncthreads();

    // ---- Per-block sum + last-block-done global reduction ---------------
    if (tid == 0) {
        float bs = 0.f;
        #pragma unroll
        for (int i = 0; i < 8; i++) bs += wsum[i];
        g_bsum[bid] = bs;
        __threadfence();
        const int old = atomicAdd(&g_cnt, 1);
        s_last = (old == NBLK - 1) ? 1 : 0;
    }
    __syncthreads();

    if (s_last) {
        __threadfence();
        double acc0 = 0.0, acc1 = 0.0, acc2 = 0.0, acc3 = 0.0;
        #pragma unroll 1
        for (int i = tid; i < NBLK; i += 1024) {   // 12 iterations, 4-way MLP
            acc0 += (double)g_bsum[i];
            acc1 += (double)g_bsum[i + 256];
            acc2 += (double)g_bsum[i + 512];
            acc3 += (double)g_bsum[i + 768];
        }
        double d = (acc0 + acc1) + (acc2 + acc3);
        #pragma unroll
        for (int o = 16; o > 0; o >>= 1)
            d += __shfl_xor_sync(0xffffffffu, d, o);
        if (lane == 0) dsum[wrp] = d;
        __syncthreads();
        if (tid == 0) {
            double tot = 0.0;
            #pragma unroll
            for (int i = 0; i < 8; i++) tot += dsum[i];
            out[0] = (float)(1.0 - tot / 12582912.0);   // 16*3*512*512
            g_cnt = 0;                                   // reset for next replay
        }
    }
}

extern "C" void kernel_launch(void* const* d_in, const int* in_sizes, int n_in,
                              void* d_out, int out_size)
{
    const float* pred   = (const float*)d_in[0];
    const float* target = (const float*)d_in[1];
    (void)in_sizes; (void)n_in; (void)out_size;

    dim3 grid(TILES, NIMG);   // (256, 48)
    ssim_fused<<<grid, 256>>>(pred, target, (float*)d_out);
}

// round 5
// speedup vs baseline: 1.0161x; 1.0161x over previous
#include <cuda_runtime.h>

// SSIM loss, single fused kernel, f32x2-packed separable blur.
// pred/target: (16,3,512,512) f32. Output: scalar f32 = 1 - mean(ssim_map).

#define RAD 5
#define TX 32
#define TY 32
#define PH 42                 // TY + 2*RAD
#define PW 42                 // TX + 2*RAD
#define HB4_PITCH 33          // float4 pitch for hb1234 (odd -> STS.128 conflict-free)
#define HB5_PITCH 36          // float pitch for hb5
#define IMG 512
#define NIMG 48
#define TILES 256             // 16 x 16 tiles per image
#define NBLK (TILES * NIMG)   // 12288
#define SSIM_C1 1.0e-4f
#define SSIM_C2 9.0e-4f

__device__ float g_bsum[NBLK];
__device__ int g_cnt;         // zero-init; last block resets each run

union F2U { float2 f; unsigned long long u; };

__device__ __forceinline__ unsigned long long pack2(float x, float y) {
    unsigned long long r;
    asm("mov.b64 %0, {%1, %2};" : "=l"(r) : "f"(x), "f"(y));
    return r;
}
__device__ __forceinline__ unsigned long long fma2(unsigned long long a,
                                                   unsigned long long b,
                                                   unsigned long long c) {
    unsigned long long d;
    asm("fma.rn.f32x2 %0, %1, %2, %3;" : "=l"(d) : "l"(a), "l"(b), "l"(c));
    return d;
}
__device__ __forceinline__ unsigned long long mul2(unsigned long long a,
                                                   unsigned long long b) {
    unsigned long long d;
    asm("mul.rn.f32x2 %0, %1, %2;" : "=l"(d) : "l"(a), "l"(b));
    return d;
}

__global__ __launch_bounds__(256, 5)
void ssim_fused(const float* __restrict__ pred,
                const float* __restrict__ target,
                float* __restrict__ out)
{
    __shared__ float2 spt[PH][PW];            // (p,t) interleaved
    __shared__ float4 hb1234[PH][HB4_PITCH];  // (h(p), h(t), h(p^2), h(t^2))
    __shared__ float  hb5[PH][HB5_PITCH];     // h(p*t)
    __shared__ float  wsum[4];
    __shared__ double dsum[8];
    __shared__ int    s_last;

    // Normalized 1-D Gaussian, sigma=1.5, size 11.
    const float GWs[11] = {
        0.00102838f, 0.00759876f, 0.03600077f, 0.10936069f, 0.21300553f,
        0.26601173f,
        0.21300553f, 0.10936069f, 0.03600077f, 0.00759876f, 0.00102838f
    };
    unsigned long long GWp[11];
    #pragma unroll
    for (int k = 0; k < 11; k++) GWp[k] = pack2(GWs[k], GWs[k]);
    const unsigned long long NEG1 = pack2(-1.0f, -1.0f);

    const int tid  = threadIdx.x;
    const int lane = tid & 31;
    const int wrp  = tid >> 5;

    const int tile_x = blockIdx.x & 15;
    const int tile_y = blockIdx.x >> 4;
    const int bid    = blockIdx.y * TILES + blockIdx.x;
    const float* pb = pred   + (size_t)blockIdx.y * IMG * IMG;
    const float* tb = target + (size_t)blockIdx.y * IMG * IMG;
    const int x0 = tile_x * TX - RAD;
    const int y0 = tile_y * TY - RAD;

    // ---- Phase 1: load 42x42 halo, interleave (p,t) ---------------------
    #pragma unroll 1
    for (int r = wrp; r < PH; r += 8) {
        const int gy = y0 + r;
        const bool rok = ((unsigned)gy < (unsigned)IMG);
        const float* prow = pb + gy * IMG;
        const float* trow = tb + gy * IMG;
        {
            const int gx = x0 + lane;
            const bool ok = rok && ((unsigned)gx < (unsigned)IMG);
            spt[r][lane] = make_float2(ok ? __ldg(prow + gx) : 0.f,
                                       ok ? __ldg(trow + gx) : 0.f);
        }
        if (lane < PW - 32) {
            const int gx = x0 + lane + 32;
            const bool ok = rok && ((unsigned)gx < (unsigned)IMG);
            spt[r][lane + 32] = make_float2(ok ? __ldg(prow + gx) : 0.f,
                                            ok ? __ldg(trow + gx) : 0.f);
        }
    }
    __syncthreads();

    // ---- Phase 2: horizontal blur. Warp w owns output cols 4w..4w+3; ----
    // rows from lane (r = lane, then 32+lane for lane<10). No div/mod.
    {
        const int cx = wrp * 4;
        #pragma unroll
        for (int step = 0; step < 2; step++) {
            const int r = lane + 32 * step;
            if (step == 0 || r < PH) {
                float4 raw[7];
                const float4* rp = reinterpret_cast<const float4*>(&spt[r][cx]);
                #pragma unroll
                for (int q = 0; q < 7; q++) raw[q] = rp[q];

                F2U acc12[4], acc34[4];
                float acc5[4];
                #pragma unroll
                for (int j = 0; j < 4; j++) {
                    acc12[j].f = make_float2(0.f, 0.f);
                    acc34[j].f = make_float2(0.f, 0.f);
                    acc5[j] = 0.f;
                }

                #pragma unroll
                for (int k = 0; k < 14; k++) {
                    F2U e;
                    e.f.x = (k & 1) ? raw[k >> 1].z : raw[k >> 1].x;
                    e.f.y = (k & 1) ? raw[k >> 1].w : raw[k >> 1].y;
                    F2U sq; sq.u = mul2(e.u, e.u);
                    const float x = e.f.x * e.f.y;
                    #pragma unroll
                    for (int j = 0; j < 4; j++) {
                        const int w = k - j;
                        if (w >= 0 && w < 11) {
                            acc12[j].u = fma2(GWp[w], e.u,  acc12[j].u);
                            acc34[j].u = fma2(GWp[w], sq.u, acc34[j].u);
                            acc5[j]    = fmaf(GWs[w], x, acc5[j]);
                        }
                    }
                }

                #pragma unroll
                for (int j = 0; j < 4; j++)
                    hb1234[r][cx + j] = make_float4(acc12[j].f.x, acc12[j].f.y,
                                                    acc34[j].f.x, acc34[j].f.y);
                *reinterpret_cast<float4*>(&hb5[r][cx]) =
                    make_float4(acc5[0], acc5[1], acc5[2], acc5[3]);
            }
        }
    }
    __syncthreads();

    // ---- Phase 3: vertical blur, warps 0-3, 8 rows/thread + SSIM --------
    if (wrp < 4) {
        const int c  = lane;
        const int yb = wrp * 8;

        F2U a12[8], a34[8];
        float a5[8];
        #pragma unroll
        for (int j = 0; j < 8; j++) {
            a12[j].f = make_float2(0.f, 0.f);
            a34[j].f = make_float2(0.f, 0.f);
            a5[j] = 0.f;
        }

        #pragma unroll
        for (int k = 0; k < 18; k++) {
            const float4 h = hb1234[yb + k][c];
            F2U h12; h12.f = make_float2(h.x, h.y);
            F2U h34; h34.f = make_float2(h.z, h.w);
            const float h5 = hb5[yb + k][c];
            #pragma unroll
            for (int j = 0; j < 8; j++) {
                const int w = k - j;
                if (w >= 0 && w < 11) {
                    a12[j].u = fma2(GWp[w], h12.u, a12[j].u);
                    a34[j].u = fma2(GWp[w], h34.u, a34[j].u);
                    a5[j]    = fmaf(GWs[w], h5, a5[j]);
                }
            }
        }

        float num[8], den[8];
        #pragma unroll
        for (int j = 0; j < 8; j++) {
            F2U musq; musq.u = mul2(a12[j].u, a12[j].u);        // (mu1^2, mu2^2)
            F2U sig;  sig.u  = fma2(NEG1, musq.u, a34[j].u);    // (sig1^2, sig2^2)
            const float mu12 = a12[j].f.x * a12[j].f.y;
            const float s12v = a5[j] - mu12;
            num[j] = fmaf(2.f, mu12, SSIM_C1) * fmaf(2.f, s12v, SSIM_C2);
            den[j] = (musq.f.x + musq.f.y + SSIM_C1) * (sig.f.x + sig.f.y + SSIM_C2);
        }

        // One division per 4 pixels (den >= ~9e-8; 4-way product stays normal).
        float ssum = 0.f;
        #pragma unroll
        for (int h2 = 0; h2 < 2; h2++) {
            const int b = 4 * h2;
            const float n01 = fmaf(num[b + 0], den[b + 1], num[b + 1] * den[b + 0]);
            const float d01 = den[b + 0] * den[b + 1];
            const float n23 = fmaf(num[b + 2], den[b + 3], num[b + 3] * den[b + 2]);
            const float d23 = den[b + 2] * den[b + 3];
            const float nall = fmaf(n01, d23, n23 * d01);
            const float dall = d01 * d23;
            ssum += __fdividef(nall, dall);
        }

        #pragma unroll
        for (int o = 16; o > 0; o >>= 1)
            ssum += __shfl_xor_sync(0xffffffffu, ssum, o);
        if (lane == 0) wsum[wrp] = ssum;
    }
    __syncthreads();

    // ---- Per-block sum + last-block-done global reduction ---------------
    if (tid == 0) {
        g_bsum[bid] = wsum[0] + wsum[1] + wsum[2] + wsum[3];
        __threadfence();
        const int old = atomicAdd(&g_cnt, 1);
        s_last = (old == NBLK - 1) ? 1 : 0;
    }
    __syncthreads();

    if (s_last) {
        __threadfence();
        double acc0 = 0.0, acc1 = 0.0, acc2 = 0.0, acc3 = 0.0;
        #pragma unroll 1
        for (int i = tid; i < NBLK; i += 1024) {   // 12 iterations, 4-way MLP
            acc0 += (double)g_bsum[i];
            acc1 += (double)g_bsum[i + 256];
            acc2 += (double)g_bsum[i + 512];
            acc3 += (double)g_bsum[i + 768];
        }
        double d = (acc0 + acc1) + (acc2 + acc3);
        #pragma unroll
        for (int o = 16; o > 0; o >>= 1)
            d += __shfl_xor_sync(0xffffffffu, d, o);
        if (lane == 0) dsum[wrp] = d;
        __syncthreads();
        if (tid == 0) {
            double tot = 0.0;
            #pragma unroll
            for (int i = 0; i < 8; i++) tot += dsum[i];
            out[0] = (float)(1.0 - tot / 12582912.0);   // 16*3*512*512
            g_cnt = 0;                                   // reset for next replay
        }
    }
}

extern "C" void kernel_launch(void* const* d_in, const int* in_sizes, int n_in,
                              void* d_out, int out_size)
{
    const float* pred   = (const float*)d_in[0];
    const float* target = (const float*)d_in[1];
    (void)in_sizes; (void)n_in; (void)out_size;

    dim3 grid(TILES, NIMG);   // (256, 48)
    ssim_fused<<<grid, 256>>>(pred, target, (float*)d_out);
}

// round 6
// speedup vs baseline: 1.2078x; 1.1887x over previous
#include <cuda_runtime.h>

// SSIM loss, single fused kernel, f32x2-packed separable blur.
// pred/target: (16,3,512,512) f32. Output: scalar f32 = 1 - mean(ssim_map).

#define RAD 5
#define TX 32
#define TY 32
#define PH 42                 // TY + 2*RAD
#define PW 42                 // TX + 2*RAD
#define HB4_PITCH 33          // float4 pitch: 528B = 16 mod 128 -> conflict-free
#define HB5_PITCH 36          // float pitch: 144B = 16 mod 128 -> conflict-free
#define IMG 512
#define NIMG 48
#define TILES 256             // 16 x 16 tiles per image
#define NBLK (TILES * NIMG)   // 12288
#define SSIM_C1 1.0e-4f
#define SSIM_C2 9.0e-4f

__device__ float g_bsum[NBLK];
__device__ int g_cnt;         // zero-init; last block resets each run

union F2U { float2 f; unsigned long long u; };

__device__ __forceinline__ unsigned long long pack2(float x, float y) {
    unsigned long long r;
    asm("mov.b64 %0, {%1, %2};" : "=l"(r) : "f"(x), "f"(y));
    return r;
}
__device__ __forceinline__ unsigned long long fma2(unsigned long long a,
                                                   unsigned long long b,
                                                   unsigned long long c) {
    unsigned long long d;
    asm("fma.rn.f32x2 %0, %1, %2, %3;" : "=l"(d) : "l"(a), "l"(b), "l"(c));
    return d;
}
__device__ __forceinline__ unsigned long long mul2(unsigned long long a,
                                                   unsigned long long b) {
    unsigned long long d;
    asm("mul.rn.f32x2 %0, %1, %2;" : "=l"(d) : "l"(a), "l"(b));
    return d;
}

__global__ __launch_bounds__(256, 5)
void ssim_fused(const float* __restrict__ pred,
                const float* __restrict__ target,
                float* __restrict__ out)
{
    __shared__ float2 spt[PH][PW];            // (p,t) interleaved, pitch 336B
    __shared__ float4 hb1234[PH][HB4_PITCH];  // (h(p), h(t), h(p^2), h(t^2))
    __shared__ float  hb5[PH][HB5_PITCH];     // h(p*t)
    __shared__ float  wsum[4];
    __shared__ double dsum[8];
    __shared__ int    s_last;

    // Normalized 1-D Gaussian, sigma=1.5, size 11.
    const float GWs[11] = {
        0.00102838f, 0.00759876f, 0.03600077f, 0.10936069f, 0.21300553f,
        0.26601173f,
        0.21300553f, 0.10936069f, 0.03600077f, 0.00759876f, 0.00102838f
    };
    unsigned long long GWp[11];
    #pragma unroll
    for (int k = 0; k < 11; k++) GWp[k] = pack2(GWs[k], GWs[k]);
    const unsigned long long NEG1 = pack2(-1.0f, -1.0f);

    const int tid  = threadIdx.x;
    const int lane = tid & 31;
    const int wrp  = tid >> 5;

    const int tile_x = blockIdx.x & 15;
    const int tile_y = blockIdx.x >> 4;
    const int bid    = blockIdx.y * TILES + blockIdx.x;
    const float* pb = pred   + (size_t)blockIdx.y * IMG * IMG;
    const float* tb = target + (size_t)blockIdx.y * IMG * IMG;
    const int x0 = tile_x * TX - RAD;
    const int y0 = tile_y * TY - RAD;

    // ---- Phase 1: load 42x42 halo, interleave (p,t) ---------------------
    const bool interior = (tile_x > 0) && (tile_x < 15) && (tile_y > 0) && (tile_y < 15);
    if (interior) {
        // No bounds checks: whole 42x42 window is inside the image.
        #pragma unroll 1
        for (int r = wrp; r < PH; r += 8) {
            const float* prow = pb + (y0 + r) * IMG + x0;
            const float* trow = tb + (y0 + r) * IMG + x0;
            spt[r][lane] = make_float2(__ldg(prow + lane), __ldg(trow + lane));
            if (lane < PW - 32)
                spt[r][lane + 32] = make_float2(__ldg(prow + lane + 32),
                                                __ldg(trow + lane + 32));
        }
    } else {
        #pragma unroll 1
        for (int r = wrp; r < PH; r += 8) {
            const int gy = y0 + r;
            const bool rok = ((unsigned)gy < (unsigned)IMG);
            const float* prow = pb + gy * IMG;
            const float* trow = tb + gy * IMG;
            {
                const int gx = x0 + lane;
                const bool ok = rok && ((unsigned)gx < (unsigned)IMG);
                spt[r][lane] = make_float2(ok ? __ldg(prow + gx) : 0.f,
                                           ok ? __ldg(trow + gx) : 0.f);
            }
            if (lane < PW - 32) {
                const int gx = x0 + lane + 32;
                const bool ok = rok && ((unsigned)gx < (unsigned)IMG);
                spt[r][lane + 32] = make_float2(ok ? __ldg(prow + gx) : 0.f,
                                                ok ? __ldg(trow + gx) : 0.f);
            }
        }
    }
    __syncthreads();

    // ---- Phase 2: horizontal blur, 4 output cols/thread -----------------
    // item = g*42 + r (lanes run along rows -> all LDS/STS conflict-free).
    // 336 items: half 0 = 256 threads, half 1 = 80 threads (2.5 warps).
    #pragma unroll
    for (int half = 0; half < 2; half++) {
        const int it = tid + half * 256;
        if (it < PH * 8) {
            const int g  = it / PH;
            const int r  = it - g * PH;
            const int cx = g * 4;

            float4 raw[7];
            const float4* rp = reinterpret_cast<const float4*>(&spt[r][cx]);
            #pragma unroll
            for (int q = 0; q < 7; q++) raw[q] = rp[q];

            F2U acc12[4], acc34[4];
            float acc5[4];
            #pragma unroll
            for (int j = 0; j < 4; j++) {
                acc12[j].f = make_float2(0.f, 0.f);
                acc34[j].f = make_float2(0.f, 0.f);
                acc5[j] = 0.f;
            }

            #pragma unroll
            for (int k = 0; k < 14; k++) {
                F2U e;
                e.f.x = (k & 1) ? raw[k >> 1].z : raw[k >> 1].x;
                e.f.y = (k & 1) ? raw[k >> 1].w : raw[k >> 1].y;
                F2U sq; sq.u = mul2(e.u, e.u);
                const float x = e.f.x * e.f.y;
                #pragma unroll
                for (int j = 0; j < 4; j++) {
                    const int w = k - j;
                    if (w >= 0 && w < 11) {
                        acc12[j].u = fma2(GWp[w], e.u,  acc12[j].u);
                        acc34[j].u = fma2(GWp[w], sq.u, acc34[j].u);
                        acc5[j]    = fmaf(GWs[w], x, acc5[j]);
                    }
                }
            }

            #pragma unroll
            for (int j = 0; j < 4; j++)
                hb1234[r][cx + j] = make_float4(acc12[j].f.x, acc12[j].f.y,
                                                acc34[j].f.x, acc34[j].f.y);
            *reinterpret_cast<float4*>(&hb5[r][cx]) =
                make_float4(acc5[0], acc5[1], acc5[2], acc5[3]);
        }
    }
    __syncthreads();

    // ---- Phase 3: vertical blur, warps 0-3, 8 rows/thread + SSIM --------
    if (wrp < 4) {
        const int c  = lane;
        const int yb = wrp * 8;

        F2U a12[8], a34[8];
        float a5[8];
        #pragma unroll
        for (int j = 0; j < 8; j++) {
            a12[j].f = make_float2(0.f, 0.f);
            a34[j].f = make_float2(0.f, 0.f);
            a5[j] = 0.f;
        }

        #pragma unroll
        for (int k = 0; k < 18; k++) {
            const float4 h = hb1234[yb + k][c];
            F2U h12; h12.f = make_float2(h.x, h.y);
            F2U h34; h34.f = make_float2(h.z, h.w);
            const float h5 = hb5[yb + k][c];
            #pragma unroll
            for (int j = 0; j < 8; j++) {
                const int w = k - j;
                if (w >= 0 && w < 11) {
                    a12[j].u = fma2(GWp[w], h12.u, a12[j].u);
                    a34[j].u = fma2(GWp[w], h34.u, a34[j].u);
                    a5[j]    = fmaf(GWs[w], h5, a5[j]);
                }
            }
        }

        float num[8], den[8];
        #pragma unroll
        for (int j = 0; j < 8; j++) {
            F2U musq; musq.u = mul2(a12[j].u, a12[j].u);        // (mu1^2, mu2^2)
            F2U sig;  sig.u  = fma2(NEG1, musq.u, a34[j].u);    // (sig1^2, sig2^2)
            const float mu12 = a12[j].f.x * a12[j].f.y;
            const float s12v = a5[j] - mu12;
            num[j] = fmaf(2.f, mu12, SSIM_C1) * fmaf(2.f, s12v, SSIM_C2);
            den[j] = (musq.f.x + musq.f.y + SSIM_C1) * (sig.f.x + sig.f.y + SSIM_C2);
        }

        // One division per 4 pixels (den >= ~9e-8; 4-way product stays normal).
        float ssum = 0.f;
        #pragma unroll
        for (int h2 = 0; h2 < 2; h2++) {
            const int b = 4 * h2;
            const float n01 = fmaf(num[b + 0], den[b + 1], num[b + 1] * den[b + 0]);
            const float d01 = den[b + 0] * den[b + 1];
            const float n23 = fmaf(num[b + 2], den[b + 3], num[b + 3] * den[b + 2]);
            const float d23 = den[b + 2] * den[b + 3];
            const float nall = fmaf(n01, d23, n23 * d01);
            const float dall = d01 * d23;
            ssum += __fdividef(nall, dall);
        }

        #pragma unroll
        for (int o = 16; o > 0; o >>= 1)
            ssum += __shfl_xor_sync(0xffffffffu, ssum, o);
        if (lane == 0) wsum[wrp] = ssum;
    }
    __syncthreads();

    // ---- Per-block sum + last-block-done global reduction ---------------
    if (tid == 0) {
        g_bsum[bid] = wsum[0] + wsum[1] + wsum[2] + wsum[3];
        __threadfence();
        const int old = atomicAdd(&g_cnt, 1);
        s_last = (old == NBLK - 1) ? 1 : 0;
    }
    __syncthreads();

    if (s_last) {
        __threadfence();
        double acc0 = 0.0, acc1 = 0.0, acc2 = 0.0, acc3 = 0.0;
        #pragma unroll 1
        for (int i = tid; i < NBLK; i += 1024) {   // 12 iterations, 4-way MLP
            acc0 += (double)g_bsum[i];
            acc1 += (double)g_bsum[i + 256];
            acc2 += (double)g_bsum[i + 512];
            acc3 += (double)g_bsum[i + 768];
        }
        double d = (acc0 + acc1) + (acc2 + acc3);
        #pragma unroll
        for (int o = 16; o > 0; o >>= 1)
            d += __shfl_xor_sync(0xffffffffu, d, o);
        if (lane == 0) dsum[wrp] = d;
        __syncthreads();
        if (tid == 0) {
            double tot = 0.0;
            #pragma unroll
            for (int i = 0; i < 8; i++) tot += dsum[i];
            out[0] = (float)(1.0 - tot / 12582912.0);   // 16*3*512*512
            g_cnt = 0;                                   // reset for next replay
        }
    }
}

extern "C" void kernel_launch(void* const* d_in, const int* in_sizes, int n_in,
                              void* d_out, int out_size)
{
    const float* pred   = (const float*)d_in[0];
    const float* target = (const float*)d_in[1];
    (void)in_sizes; (void)n_in; (void)out_size;

    dim3 grid(TILES, NIMG);   // (256, 48)
    ssim_fused<<<grid, 256>>>(pred, target, (float*)d_out);
}